// round 12
// baseline (speedup 1.0000x reference)
#include <cuda_runtime.h>
#include <cstdint>
#include <cstddef>

#define NA 4096
#define TT 512
#define TS 384
#define AS 128
#define AZ 16
#define NFEAT 388

typedef unsigned long long ull;

__device__ int   g_tok[NA];
__device__ float g_s2c[TT * AS];
__device__ float g_cq[NA * AZ];
__device__ float g_ck[NA * AZ];

// ---- packed f32x2 helpers ----
__device__ __forceinline__ ull pk2(float lo, float hi) {
    ull r; asm("mov.b64 %0,{%1,%2};" : "=l"(r) : "f"(lo), "f"(hi)); return r;
}
__device__ __forceinline__ void upk2(ull v, float& lo, float& hi) {
    asm("mov.b64 {%0,%1},%2;" : "=f"(lo), "=f"(hi) : "l"(v));
}
__device__ __forceinline__ ull fma2(ull a, ull b, ull c) {
    ull r; asm("fma.rn.f32x2 %0,%1,%2,%3;" : "=l"(r) : "l"(a), "l"(b), "l"(c)); return r;
}
__device__ __forceinline__ ull add2(ull a, ull b) {
    ull r; asm("add.rn.f32x2 %0,%1,%2;" : "=l"(r) : "l"(a), "l"(b)); return r;
}
__device__ __forceinline__ ull relu2(ull v) {
    float lo, hi; upk2(v, lo, hi);
    return pk2(fmaxf(lo, 0.f), fmaxf(hi, 0.f));
}

// ---- kernel 1: fused prep ----
// blocks [0,256):   tok argmax, 16 atom rows each (memory-bound — scheduled FIRST)
// blocks [256,320): s2c tiled GEMM (8 token rows each)
__global__ void __launch_bounds__(256) prep_kernel(
    const float* __restrict__ a2t,
    const float* __restrict__ s_trunk,
    const float* __restrict__ g, const float* __restrict__ b,
    const float* __restrict__ W) {
    int tid = threadIdx.x;
    int wid = tid >> 5, lane = tid & 31;
    if (blockIdx.x < 256) {
        int row0 = blockIdx.x * 16 + wid * 2;
        const float4* r0 = (const float4*)(a2t + (size_t)row0 * TT);
        const float4* r1 = (const float4*)(a2t + (size_t)(row0 + 1) * TT);
        float4 v0[4], v1[4];
#pragma unroll
        for (int i = 0; i < 4; i++) v0[i] = r0[lane + i * 32];
#pragma unroll
        for (int i = 0; i < 4; i++) v1[i] = r1[lane + i * 32];
        int f0 = -1, f1 = -1;
#pragma unroll
        for (int i = 0; i < 4; i++) {
            int j = (lane + i * 32) * 4;
            if (v0[i].x > 0.5f) f0 = j;
            if (v0[i].y > 0.5f) f0 = j + 1;
            if (v0[i].z > 0.5f) f0 = j + 2;
            if (v0[i].w > 0.5f) f0 = j + 3;
            if (v1[i].x > 0.5f) f1 = j;
            if (v1[i].y > 0.5f) f1 = j + 1;
            if (v1[i].z > 0.5f) f1 = j + 2;
            if (v1[i].w > 0.5f) f1 = j + 3;
        }
#pragma unroll
        for (int d = 16; d; d >>= 1) {
            f0 = max(f0, __shfl_xor_sync(~0u, f0, d));
            f1 = max(f1, __shfl_xor_sync(~0u, f1, d));
        }
        if (lane == 0) { g_tok[row0] = f0; g_tok[row0 + 1] = f1; }
        return;
    }
    // --- s2c: 8 rows of LN(s_trunk) @ W_s2c ---
    __shared__ __align__(16) float As[8][392];
    __shared__ __align__(16) float Bs[32][128];
    int r0 = (blockIdx.x - 256) * 8;
    {
        const float4* src = (const float4*)(s_trunk + (size_t)(r0 + wid) * TS);
        float4 vbuf[3];
        float s = 0.f, q = 0.f;
#pragma unroll
        for (int i = 0; i < 3; i++) {
            float4 v = src[lane + i * 32];
            vbuf[i] = v;
            s += v.x + v.y + v.z + v.w;
            q += v.x * v.x + v.y * v.y + v.z * v.z + v.w * v.w;
        }
#pragma unroll
        for (int d = 16; d; d >>= 1) { s += __shfl_xor_sync(~0u, s, d); q += __shfl_xor_sync(~0u, q, d); }
        float mean = s / TS;
        float rstd = rsqrtf(q / TS - mean * mean + 1e-5f);
#pragma unroll
        for (int i = 0; i < 3; i++) {
            int f = (lane + i * 32) * 4;
            float4 v = vbuf[i];
            float4 g4 = *(const float4*)&g[f];
            float4 b4 = *(const float4*)&b[f];
            float4 o4;
            o4.x = (v.x - mean) * rstd * g4.x + b4.x;
            o4.y = (v.y - mean) * rstd * g4.y + b4.y;
            o4.z = (v.z - mean) * rstd * g4.z + b4.z;
            o4.w = (v.w - mean) * rstd * g4.w + b4.w;
            *(float4*)&As[wid][f] = o4;
        }
    }
    __syncthreads();

    const int row = wid;
    const int c0 = lane * 4;
    float4 acc = { 0.f, 0.f, 0.f, 0.f };
    for (int kt = 0; kt < 12; kt++) {
#pragma unroll
        for (int i = 0; i < 4; i++) {
            int e = (tid + i * 256) * 4;
            int kk = e >> 7, col = e & 127;
            *(float4*)&Bs[kk][col] = *(const float4*)&W[(size_t)(kt * 32 + kk) * AS + col];
        }
        __syncthreads();
#pragma unroll
        for (int k4 = 0; k4 < 8; k4++) {
            float4 a4 = *(const float4*)&As[row][kt * 32 + k4 * 4];
            float av[4] = { a4.x, a4.y, a4.z, a4.w };
#pragma unroll
            for (int e = 0; e < 4; e++) {
                float4 b4 = *(const float4*)&Bs[k4 * 4 + e][c0];
                acc.x += av[e] * b4.x; acc.y += av[e] * b4.y;
                acc.z += av[e] * b4.z; acc.w += av[e] * b4.w;
            }
        }
        __syncthreads();
    }
    *(float4*)&g_s2c[(size_t)(r0 + row) * AS + c0] = acc;
}

// ---- kernel 2: c0 = feats@W_feat+b ; q,c outputs ; fused cq/ck ----
#define C0_REGION1 16384
__global__ void __launch_bounds__(256) c0_kernel(
    const float* __restrict__ pos, const float* __restrict__ charge,
    const float* __restrict__ elem, const float* __restrict__ chars,
    const float* __restrict__ Wf, const float* __restrict__ bf,
    const float* __restrict__ Wcq, const float* __restrict__ Wck,
    float* __restrict__ out_q, float* __restrict__ out_c) {
    __shared__ __align__(16) char buf[C0_REGION1];
    __shared__ float cs[32][129];
    float (*As)[40] = (float(*)[40])buf;
    float* Bs = (float*)(buf + 16 * 40 * 4);
    float* ws = (float*)buf;

    int tid = threadIdx.x, ty = tid >> 5, tx = tid & 31;
    int m0 = blockIdx.x * 32;
    float acc[4][4] = {};
    for (int kt = 0; kt < 25; kt++) {
        int fbase = kt * 16;
#pragma unroll
        for (int j = 0; j < 2; j++) {
            int e = tid + j * 256;
            int kk = e & 15, m = e >> 4;
            int f = fbase + kk, n = m0 + m;
            float v = 0.f;
            if (f < NFEAT) {
                if (f < 3)        v = pos[n * 3 + f];
                else if (f == 3)  v = charge[n];
                else if (f < 132) v = elem[(size_t)n * 128 + f - 4];
                else              v = chars[(size_t)n * 256 + f - 132];
            }
            As[kk][m] = v;
        }
#pragma unroll
        for (int j = 0; j < 8; j++) {
            int e = tid + j * 256;
            int kk = e >> 7, n = e & 127;
            int f = fbase + kk;
            Bs[kk * 128 + n] = (f < NFEAT) ? Wf[(size_t)f * AS + n] : 0.f;
        }
        __syncthreads();
#pragma unroll
        for (int kk = 0; kk < 16; kk++) {
            float4 a4 = *(const float4*)&As[kk][ty * 4];
            float4 b4 = *(const float4*)&Bs[kk * 128 + tx * 4];
            float av[4] = { a4.x, a4.y, a4.z, a4.w };
            float bv[4] = { b4.x, b4.y, b4.z, b4.w };
#pragma unroll
            for (int i = 0; i < 4; i++)
#pragma unroll
                for (int j = 0; j < 4; j++) acc[i][j] += av[i] * bv[j];
        }
        __syncthreads();
    }
    for (int i = tid; i < 128 * 32; i += 256) {
        int f = i >> 5, j = i & 31;
        ws[i] = (j < 16) ? Wcq[f * 16 + j] : Wck[f * 16 + (j - 16)];
    }
    float4 bfv = *(const float4*)&bf[tx * 4];
#pragma unroll
    for (int i = 0; i < 4; i++) {
        int n = m0 + ty * 4 + i;
        int t = g_tok[n];
        float4 qv;
        qv.x = acc[i][0] + bfv.x; qv.y = acc[i][1] + bfv.y;
        qv.z = acc[i][2] + bfv.z; qv.w = acc[i][3] + bfv.w;
        *(float4*)&out_q[(size_t)n * AS + tx * 4] = qv;
        float4 sv = *(const float4*)&g_s2c[(size_t)t * AS + tx * 4];
        float4 cv = { qv.x + sv.x, qv.y + sv.y, qv.z + sv.z, qv.w + sv.w };
        *(float4*)&out_c[(size_t)n * AS + tx * 4] = cv;
        int a = ty * 4 + i;
        cs[a][tx * 4 + 0] = fmaxf(cv.x, 0.f);
        cs[a][tx * 4 + 1] = fmaxf(cv.y, 0.f);
        cs[a][tx * 4 + 2] = fmaxf(cv.z, 0.f);
        cs[a][tx * 4 + 3] = fmaxf(cv.w, 0.f);
    }
    __syncthreads();
    {
        int a = tid >> 3, jg = tid & 7, j0 = jg * 4;
        float4 a4 = { 0.f, 0.f, 0.f, 0.f };
#pragma unroll 8
        for (int f = 0; f < 128; f++) {
            float r = cs[a][f];
            float4 w4 = *(const float4*)&ws[f * 32 + j0];
            a4.x += r * w4.x; a4.y += r * w4.y; a4.z += r * w4.z; a4.w += r * w4.w;
        }
        if (j0 < 16) *(float4*)&g_cq[(m0 + a) * 16 + j0] = a4;
        else         *(float4*)&g_ck[(m0 + a) * 16 + (j0 - 16)] = a4;
    }
}

// ---- kernel 3: main p kernel (CTA = (k, chunk), grid 512 x 256 thr, 2 CTA/SM) ----
struct alignas(16) SmemP {
    ull   wm1p[256], wm2pT[256], wm3p[256];
    float tile[1024 * 17];
    float ck[128 * 17];
    float cq[32 * 16];
    float wz2pT[16 * 128];
    float wposT[48];
    float wdist[16], wmask[16];
    float lnzg[128], lnzb[128];
    float posq[32 * 4];
    float posk[128 * 4];
    int   uidq[32], uidk[128];
    int   qt[32], kt[128];
    int   qi[32], ki[128];
    int   uqt[32], ukt[128];
    int   nq, nkc[4];
    unsigned char mq[32], mk[128];
};

__device__ __forceinline__ void preacc(const SmemP& sm, int w, int l, int nk,
                                       int ktl, float* acc) {
    const float* cqr = sm.cq + w * 16;
#pragma unroll
    for (int o = 0; o < 16; o++) acc[o] = cqr[o];
    if (ktl >= 0) {
        const float* ckr = sm.ck + l * 17;
        const float* tr = sm.tile + (sm.qi[w] * nk + sm.ki[l]) * 17;
#pragma unroll
        for (int o = 0; o < 16; o++) acc[o] += ckr[o] + tr[o];
        if (sm.mk[l] && sm.mq[w] && sm.uidk[l] == sm.uidq[w]) {
            float dx = sm.posk[l * 4 + 0] - sm.posq[w * 4 + 0];
            float dy = sm.posk[l * 4 + 1] - sm.posq[w * 4 + 1];
            float dz = sm.posk[l * 4 + 2] - sm.posq[w * 4 + 2];
            float dn = 1.f / (1.f + dx * dx + dy * dy + dz * dz);
#pragma unroll
            for (int o = 0; o < 16; o++)
                acc[o] += dx * sm.wposT[o] + dy * sm.wposT[16 + o] +
                          dz * sm.wposT[32 + o] + dn * sm.wdist[o] + sm.wmask[o];
        }
    }
}

__device__ __forceinline__ void zp_reduce_store(const SmemP& sm, float4 v, int lane,
                                                float* dst, int p) {
    float s = v.x + v.y + v.z + v.w;
    float q = v.x * v.x + v.y * v.y + v.z * v.z + v.w * v.w;
#pragma unroll
    for (int d = 16; d; d >>= 1) { s += __shfl_xor_sync(~0u, s, d); q += __shfl_xor_sync(~0u, q, d); }
    float mean = s * (1.f / 128.f);
    float rstd = rsqrtf(q * (1.f / 128.f) - mean * mean + 1e-5f);
    float4 g4 = ((const float4*)sm.lnzg)[lane];
    float4 b4 = ((const float4*)sm.lnzb)[lane];
    float n0 = (v.x - mean) * rstd * g4.x + b4.x;
    float n1 = (v.y - mean) * rstd * g4.y + b4.y;
    float n2 = (v.z - mean) * rstd * g4.z + b4.z;
    float n3 = (v.w - mean) * rstd * g4.w + b4.w;
    float vv[16];
#pragma unroll
    for (int o = 0; o < 16; o++) {
        float4 w = ((const float4*)(sm.wz2pT + o * 128))[lane];
        vv[o] = n0 * w.x + n1 * w.y + n2 * w.z + n3 * w.w;
    }
#pragma unroll
    for (int d = 0; d < 4; d++) {
        int half = 8 >> d;
        unsigned m = 1u << d;
        bool up = (lane & m) != 0;
        float tmp[8];
#pragma unroll
        for (int i = 0; i < 8; i++) {
            if (i < half) {
                float mine  = up ? vv[i + half] : vv[i];
                float sendv = up ? vv[i] : vv[i + half];
                tmp[i] = mine + __shfl_xor_sync(~0u, sendv, m);
            }
        }
#pragma unroll
        for (int i = 0; i < 8; i++) if (i < half) vv[i] = tmp[i];
    }
    vv[0] += __shfl_xor_sync(~0u, vv[0], 16);
    if (lane < 16) {
        int rev = ((lane & 1) << 3) | ((lane & 2) << 1) | ((lane & 4) >> 1) | ((lane & 8) >> 3);
        dst[p * 17 + rev] = vv[0];
    }
}

__global__ void __launch_bounds__(256, 2) p_kernel(
    const float* __restrict__ z, const float* __restrict__ pos,
    const int* __restrict__ maskw, const int* __restrict__ uid,
    const float* __restrict__ Wpos, const float* __restrict__ Wdist_,
    const float* __restrict__ Wmask_,
    const float* __restrict__ lnzg, const float* __restrict__ lnzb,
    const float* __restrict__ Wz2p,
    const float* __restrict__ Wm1, const float* __restrict__ Wm2,
    const float* __restrict__ Wm3,
    float* __restrict__ outp) {
    extern __shared__ char smraw[];
    SmemP& sm = *reinterpret_cast<SmemP*>(smraw);
    const int tid = threadIdx.x;
    const int k = blockIdx.x >> 2;
    const int lc = blockIdx.x & 3;

    if (tid < 128) {
        int l = tid, a = k * 32 + l - 48;
        bool valid = (a >= 0 && a < NA);
        sm.kt[l]   = valid ? g_tok[a] : -1;
        sm.uidk[l] = valid ? uid[a]   : -1;
        sm.mk[l]   = valid ? (maskw[a] != 0) : 0;
        sm.posk[l * 4 + 0] = valid ? pos[a * 3 + 0] : 0.f;
        sm.posk[l * 4 + 1] = valid ? pos[a * 3 + 1] : 0.f;
        sm.posk[l * 4 + 2] = valid ? pos[a * 3 + 2] : 0.f;
    }
    if (tid < 32) {
        int a = k * 32 + tid;
        sm.qt[tid] = g_tok[a];
        sm.uidq[tid] = uid[a];
        sm.mq[tid] = (maskw[a] != 0);
        sm.posq[tid * 4 + 0] = pos[a * 3 + 0];
        sm.posq[tid * 4 + 1] = pos[a * 3 + 1];
        sm.posq[tid * 4 + 2] = pos[a * 3 + 2];
    }
    for (int i = tid; i < 128 * 16; i += 256) {
        int l = i >> 4, o = i & 15;
        int a = k * 32 + l - 48;
        sm.ck[l * 17 + o] = (a >= 0 && a < NA) ? g_ck[a * 16 + o] : 0.f;
    }
    for (int i = tid; i < 32 * 16; i += 256) sm.cq[i] = g_cq[(k * 32) * 16 + i];
    for (int i = tid; i < 16 * 128; i += 256) {
        int o = i >> 7, f = i & 127;
        sm.wz2pT[i] = Wz2p[f * 16 + o];
    }
    if (tid < 48) sm.wposT[tid] = Wpos[tid];
    if (tid >= 64 && tid < 80)  sm.wdist[tid - 64] = Wdist_[tid - 64];
    if (tid >= 96 && tid < 112) sm.wmask[tid - 96] = Wmask_[tid - 96];
    {
        int i = tid;
        float w1 = Wm1[i];
        float w2t = Wm2[(i & 15) * 16 + (i >> 4)];
        float w3 = Wm3[i];
        sm.wm1p[i]  = pk2(w1, w1);
        sm.wm2pT[i] = pk2(w2t, w2t);
        sm.wm3p[i]  = pk2(w3, w3);
    }
    for (int i = tid; i < 128; i += 256) { sm.lnzg[i] = lnzg[i]; sm.lnzb[i] = lnzb[i]; }
    __syncthreads();

    // parallel dedup: warp 0 = q tokens, warp 1 = this chunk's k tokens
    if (tid < 32) {
        int t = sm.qt[tid];
        int prev = __shfl_up_sync(~0u, t, 1);
        bool bd = (tid == 0) || (t != prev);
        unsigned m = __ballot_sync(~0u, bd);
        int idx = __popc(m & (0xFFFFFFFFu >> (31 - tid))) - 1;
        sm.qi[tid] = idx;
        if (bd) sm.uqt[idx] = t;
        if (tid == 0) sm.nq = __popc(m);
    } else if (tid < 64) {
        int j = tid - 32;
        int l = lc * 32 + j;
        int t = sm.kt[l];
        bool valid = (t >= 0);
        int prev = __shfl_up_sync(~0u, t, 1);
        bool bd = valid && (j == 0 || t != prev);
        unsigned m = __ballot_sync(~0u, bd);
        int idx = __popc(m & (0xFFFFFFFFu >> (31 - j))) - 1;
        sm.ki[l] = valid ? idx : -1;
        if (bd) sm.ukt[lc * 32 + idx] = t;
        if (j == 0) sm.nkc[lc] = __popc(m);
    }
    __syncthreads();

    const int wid = tid >> 5, lane = tid & 31;
    const int nq = sm.nq;
    const int nk = sm.nkc[lc];
    const int npairs = nq * nk;

    for (int p = wid; p < npairs; p += 8) {
        int ti = sm.uqt[p / nk];
        int tj = sm.ukt[lc * 32 + p % nk];
        float4 v = ((const float4*)(z + ((size_t)ti * TT + tj) * 128))[lane];
        zp_reduce_store(sm, v, lane, sm.tile, p);
    }
    __syncthreads();

    const int l = lc * 32 + lane;
    const int ktl = sm.kt[l];
#pragma unroll 1
    for (int wi = 0; wi < 2; wi++) {
        const int w = wid + wi * 8;
        float accA[16], accB[16];
        preacc(sm, w, l, nk, ktl, accA);
        preacc(sm, w + 16, l, nk, ktl, accB);
        ull acc2[16];
#pragma unroll
        for (int o = 0; o < 16; o++) acc2[o] = pk2(accA[o], accB[o]);

        const ulonglong2* w1v = (const ulonglong2*)sm.wm1p;
        const ulonglong2* w2v = (const ulonglong2*)sm.wm2pT;
        const ulonglong2* w3v = (const ulonglong2*)sm.wm3p;

        ull t1[16];
#pragma unroll
        for (int j = 0; j < 16; j++) t1[j] = 0ull;
#pragma unroll
        for (int o = 0; o < 16; o++) {
            ull r2 = relu2(acc2[o]);
            const ulonglong2* row = w1v + o * 8;
#pragma unroll
            for (int jv = 0; jv < 8; jv++) {
                ulonglong2 wv = row[jv];
                t1[2 * jv]     = fma2(r2, wv.x, t1[2 * jv]);
                t1[2 * jv + 1] = fma2(r2, wv.y, t1[2 * jv + 1]);
            }
        }
#pragma unroll
        for (int o = 0; o < 16; o++) t1[o] = relu2(t1[o]);

#pragma unroll
        for (int j = 0; j < 16; j++) {
            const ulonglong2* row2 = w2v + j * 8;
            ull s0 = 0ull, s1 = 0ull, s2 = 0ull, s3 = 0ull;
#pragma unroll
            for (int i = 0; i < 8; i += 2) {
                ulonglong2 wa = row2[i], wb = row2[i + 1];
                s0 = fma2(t1[2 * i],     wa.x, s0);
                s1 = fma2(t1[2 * i + 1], wa.y, s1);
                s2 = fma2(t1[2 * i + 2], wb.x, s2);
                s3 = fma2(t1[2 * i + 3], wb.y, s3);
            }
            ull r2 = relu2(add2(add2(s0, s1), add2(s2, s3)));
            const ulonglong2* row3 = w3v + j * 8;
#pragma unroll
            for (int ov = 0; ov < 8; ov++) {
                ulonglong2 wv = row3[ov];
                acc2[2 * ov]     = fma2(r2, wv.x, acc2[2 * ov]);
                acc2[2 * ov + 1] = fma2(r2, wv.y, acc2[2 * ov + 1]);
            }
        }
#pragma unroll
        for (int o = 0; o < 16; o++) upk2(acc2[o], accA[o], accB[o]);
        float* poA = outp + (((size_t)(k * 32 + w)) * 128 + l) * 16;
        float* poB = outp + (((size_t)(k * 32 + w + 16)) * 128 + l) * 16;
#pragma unroll
        for (int oq = 0; oq < 4; oq++) {
            float4 vA = { accA[oq * 4], accA[oq * 4 + 1], accA[oq * 4 + 2], accA[oq * 4 + 3] };
            float4 vB = { accB[oq * 4], accB[oq * 4 + 1], accB[oq * 4 + 2], accB[oq * 4 + 3] };
            reinterpret_cast<float4*>(poA)[oq] = vA;
            reinterpret_cast<float4*>(poB)[oq] = vB;
        }
    }
}

extern "C" void kernel_launch(void* const* d_in, const int* in_sizes, int n_in,
                              void* d_out, int out_size) {
    const float* ref_pos      = (const float*)d_in[0];
    const float* ref_charge   = (const float*)d_in[1];
    const float* ref_element  = (const float*)d_in[2];
    const float* ref_chars    = (const float*)d_in[3];
    const int*   mask         = (const int*)d_in[4];
    const int*   uid          = (const int*)d_in[5];
    const float* a2t          = (const float*)d_in[6];
    const float* s_trunk      = (const float*)d_in[7];
    const float* z            = (const float*)d_in[8];
    const float* W_feat       = (const float*)d_in[9];
    const float* b_feat       = (const float*)d_in[10];
    const float* W_pos        = (const float*)d_in[11];
    const float* W_dist       = (const float*)d_in[12];
    const float* W_mask       = (const float*)d_in[13];
    const float* ln_s_g       = (const float*)d_in[14];
    const float* ln_s_b       = (const float*)d_in[15];
    const float* W_s2c        = (const float*)d_in[16];
    const float* ln_z_g       = (const float*)d_in[17];
    const float* ln_z_b       = (const float*)d_in[18];
    const float* W_z2p        = (const float*)d_in[19];
    const float* W_cq         = (const float*)d_in[20];
    const float* W_ck         = (const float*)d_in[21];
    const float* W_m1         = (const float*)d_in[22];
    const float* W_m2         = (const float*)d_in[23];
    const float* W_m3         = (const float*)d_in[24];

    float* out_q = (float*)d_out;
    float* out_c = out_q + (size_t)NA * AS;
    float* out_p = out_q + (size_t)2 * NA * AS;

    cudaFuncSetAttribute(p_kernel, cudaFuncAttributeMaxDynamicSharedMemorySize,
                         (int)sizeof(SmemP));

    prep_kernel<<<320, 256>>>(a2t, s_trunk, ln_s_g, ln_s_b, W_s2c);
    c0_kernel<<<128, 256>>>(ref_pos, ref_charge, ref_element, ref_chars,
                            W_feat, b_feat, W_cq, W_ck, out_q, out_c);
    p_kernel<<<512, 256, sizeof(SmemP)>>>(z, ref_pos, mask, uid,
                                          W_pos, W_dist, W_mask,
                                          ln_z_g, ln_z_b, W_z2p,
                                          W_m1, W_m2, W_m3, out_p);
}

// round 13
// speedup vs baseline: 1.0150x; 1.0150x over previous
#include <cuda_runtime.h>
#include <cstdint>
#include <cstddef>

#define NA 4096
#define TT 512
#define TS 384
#define AS 128
#define AZ 16
#define NFEAT 388

typedef unsigned long long ull;

__device__ int   g_tok[NA];
__device__ float g_s2c[TT * AS];
__device__ float g_cq[NA * AZ];
__device__ float g_ck[NA * AZ];

// ---- packed f32x2 helpers ----
__device__ __forceinline__ ull pk2(float lo, float hi) {
    ull r; asm("mov.b64 %0,{%1,%2};" : "=l"(r) : "f"(lo), "f"(hi)); return r;
}
__device__ __forceinline__ void upk2(ull v, float& lo, float& hi) {
    asm("mov.b64 {%0,%1},%2;" : "=f"(lo), "=f"(hi) : "l"(v));
}
__device__ __forceinline__ ull fma2(ull a, ull b, ull c) {
    ull r; asm("fma.rn.f32x2 %0,%1,%2,%3;" : "=l"(r) : "l"(a), "l"(b), "l"(c)); return r;
}
__device__ __forceinline__ ull add2(ull a, ull b) {
    ull r; asm("add.rn.f32x2 %0,%1,%2;" : "=l"(r) : "l"(a), "l"(b)); return r;
}
__device__ __forceinline__ ull relu2(ull v) {
    float lo, hi; upk2(v, lo, hi);
    return pk2(fmaxf(lo, 0.f), fmaxf(hi, 0.f));
}

// ---- kernel 1: s2c = LN(s_trunk) @ W_s2c (64 blocks x 8 rows) ----
__global__ void __launch_bounds__(256) s2c_kernel(
    const float* __restrict__ s_trunk,
    const float* __restrict__ g, const float* __restrict__ b,
    const float* __restrict__ W) {
    __shared__ __align__(16) float As[8][392];
    __shared__ __align__(16) float Bs[32][128];
    int tid = threadIdx.x;
    int wid = tid >> 5, lane = tid & 31;
    int r0 = blockIdx.x * 8;
    {
        const float4* src = (const float4*)(s_trunk + (size_t)(r0 + wid) * TS);
        float4 vbuf[3];
        float s = 0.f, q = 0.f;
#pragma unroll
        for (int i = 0; i < 3; i++) {
            float4 v = src[lane + i * 32];
            vbuf[i] = v;
            s += v.x + v.y + v.z + v.w;
            q += v.x * v.x + v.y * v.y + v.z * v.z + v.w * v.w;
        }
#pragma unroll
        for (int d = 16; d; d >>= 1) { s += __shfl_xor_sync(~0u, s, d); q += __shfl_xor_sync(~0u, q, d); }
        float mean = s / TS;
        float rstd = rsqrtf(q / TS - mean * mean + 1e-5f);
#pragma unroll
        for (int i = 0; i < 3; i++) {
            int f = (lane + i * 32) * 4;
            float4 v = vbuf[i];
            float4 g4 = *(const float4*)&g[f];
            float4 b4 = *(const float4*)&b[f];
            float4 o4;
            o4.x = (v.x - mean) * rstd * g4.x + b4.x;
            o4.y = (v.y - mean) * rstd * g4.y + b4.y;
            o4.z = (v.z - mean) * rstd * g4.z + b4.z;
            o4.w = (v.w - mean) * rstd * g4.w + b4.w;
            *(float4*)&As[wid][f] = o4;
        }
    }
    __syncthreads();

    const int row = wid;
    const int c0 = lane * 4;
    float4 acc = { 0.f, 0.f, 0.f, 0.f };
    for (int kt = 0; kt < 12; kt++) {
#pragma unroll
        for (int i = 0; i < 4; i++) {
            int e = (tid + i * 256) * 4;
            int kk = e >> 7, col = e & 127;
            *(float4*)&Bs[kk][col] = *(const float4*)&W[(size_t)(kt * 32 + kk) * AS + col];
        }
        __syncthreads();
#pragma unroll
        for (int k4 = 0; k4 < 8; k4++) {
            float4 a4 = *(const float4*)&As[row][kt * 32 + k4 * 4];
            float av[4] = { a4.x, a4.y, a4.z, a4.w };
#pragma unroll
            for (int e = 0; e < 4; e++) {
                float4 b4 = *(const float4*)&Bs[k4 * 4 + e][c0];
                acc.x += av[e] * b4.x; acc.y += av[e] * b4.y;
                acc.z += av[e] * b4.z; acc.w += av[e] * b4.w;
            }
        }
        __syncthreads();
    }
    *(float4*)&g_s2c[(size_t)(r0 + row) * AS + c0] = acc;
}

// ---- kernel 2: c0 = feats@W_feat+b ; inline tok argmax ; q,c ; fused cq/ck ----
#define C0_REGION1 16384
__global__ void __launch_bounds__(256) c0_kernel(
    const float* __restrict__ pos, const float* __restrict__ charge,
    const float* __restrict__ elem, const float* __restrict__ chars,
    const float* __restrict__ a2t,
    const float* __restrict__ Wf, const float* __restrict__ bf,
    const float* __restrict__ Wcq, const float* __restrict__ Wck,
    float* __restrict__ out_q, float* __restrict__ out_c) {
    __shared__ __align__(16) char buf[C0_REGION1];
    __shared__ float cs[32][129];
    __shared__ int toks[32];
    float (*As)[40] = (float(*)[40])buf;
    float* Bs = (float*)(buf + 16 * 40 * 4);
    float* ws = (float*)buf;

    int tid = threadIdx.x, ty = tid >> 5, tx = tid & 31;
    int m0 = blockIdx.x * 32;

    // inline tok: warp ty handles atoms m0+ty*4 .. m0+ty*4+3
#pragma unroll 1
    for (int rr = 0; rr < 4; rr++) {
        int m = ty * 4 + rr;
        int n = m0 + m;
        const float4* r = (const float4*)(a2t + (size_t)n * TT);
        float4 v[4];
#pragma unroll
        for (int i = 0; i < 4; i++) v[i] = r[tx + i * 32];
        int f = -1;
#pragma unroll
        for (int i = 0; i < 4; i++) {
            int j = (tx + i * 32) * 4;
            if (v[i].x > 0.5f) f = j;
            if (v[i].y > 0.5f) f = j + 1;
            if (v[i].z > 0.5f) f = j + 2;
            if (v[i].w > 0.5f) f = j + 3;
        }
#pragma unroll
        for (int d = 16; d; d >>= 1) f = max(f, __shfl_xor_sync(~0u, f, d));
        if (tx == 0) { toks[m] = f; g_tok[n] = f; }
    }

    float acc[4][4] = {};
    for (int kt = 0; kt < 25; kt++) {
        int fbase = kt * 16;
#pragma unroll
        for (int j = 0; j < 2; j++) {
            int e = tid + j * 256;
            int kk = e & 15, m = e >> 4;
            int f = fbase + kk, n = m0 + m;
            float v = 0.f;
            if (f < NFEAT) {
                if (f < 3)        v = pos[n * 3 + f];
                else if (f == 3)  v = charge[n];
                else if (f < 132) v = elem[(size_t)n * 128 + f - 4];
                else              v = chars[(size_t)n * 256 + f - 132];
            }
            As[kk][m] = v;
        }
#pragma unroll
        for (int j = 0; j < 8; j++) {
            int e = tid + j * 256;
            int kk = e >> 7, n = e & 127;
            int f = fbase + kk;
            Bs[kk * 128 + n] = (f < NFEAT) ? Wf[(size_t)f * AS + n] : 0.f;
        }
        __syncthreads();
#pragma unroll
        for (int kk = 0; kk < 16; kk++) {
            float4 a4 = *(const float4*)&As[kk][ty * 4];
            float4 b4 = *(const float4*)&Bs[kk * 128 + tx * 4];
            float av[4] = { a4.x, a4.y, a4.z, a4.w };
            float bv[4] = { b4.x, b4.y, b4.z, b4.w };
#pragma unroll
            for (int i = 0; i < 4; i++)
#pragma unroll
                for (int j = 0; j < 4; j++) acc[i][j] += av[i] * bv[j];
        }
        __syncthreads();
    }
    for (int i = tid; i < 128 * 32; i += 256) {
        int f = i >> 5, j = i & 31;
        ws[i] = (j < 16) ? Wcq[f * 16 + j] : Wck[f * 16 + (j - 16)];
    }
    float4 bfv = *(const float4*)&bf[tx * 4];
#pragma unroll
    for (int i = 0; i < 4; i++) {
        int n = m0 + ty * 4 + i;
        int t = toks[ty * 4 + i];
        float4 qv;
        qv.x = acc[i][0] + bfv.x; qv.y = acc[i][1] + bfv.y;
        qv.z = acc[i][2] + bfv.z; qv.w = acc[i][3] + bfv.w;
        *(float4*)&out_q[(size_t)n * AS + tx * 4] = qv;
        float4 sv = *(const float4*)&g_s2c[(size_t)t * AS + tx * 4];
        float4 cv = { qv.x + sv.x, qv.y + sv.y, qv.z + sv.z, qv.w + sv.w };
        *(float4*)&out_c[(size_t)n * AS + tx * 4] = cv;
        int a = ty * 4 + i;
        cs[a][tx * 4 + 0] = fmaxf(cv.x, 0.f);
        cs[a][tx * 4 + 1] = fmaxf(cv.y, 0.f);
        cs[a][tx * 4 + 2] = fmaxf(cv.z, 0.f);
        cs[a][tx * 4 + 3] = fmaxf(cv.w, 0.f);
    }
    __syncthreads();
    {
        int a = tid >> 3, jg = tid & 7, j0 = jg * 4;
        float4 a4 = { 0.f, 0.f, 0.f, 0.f };
#pragma unroll 8
        for (int f = 0; f < 128; f++) {
            float r = cs[a][f];
            float4 w4 = *(const float4*)&ws[f * 32 + j0];
            a4.x += r * w4.x; a4.y += r * w4.y; a4.z += r * w4.z; a4.w += r * w4.w;
        }
        if (j0 < 16) *(float4*)&g_cq[(m0 + a) * 16 + j0] = a4;
        else         *(float4*)&g_ck[(m0 + a) * 16 + (j0 - 16)] = a4;
    }
}

// ---- kernel 3: main p kernel (2-way split: CTA=(k,half), 256 thr, 2 CTA/SM) ----
struct alignas(16) SmemP {
    ull   wm1p[256], wm2pT[256], wm3p[256];
    float tile[1024 * 17];
    float ck[128 * 17];
    float cq[32 * 16];
    float wz2pT[16 * 128];
    float wposT[48];
    float wdist[16], wmask[16];
    float lnzg[128], lnzb[128];
    float posq[32 * 4];
    float posk[128 * 4];
    int   uidq[32], uidk[128];
    int   qt[32], kt[128];
    int   qi[32], ki[128];
    int   uqt[32], ukt[128];
    int   nq, nkc[4];
    unsigned char mq[32], mk[128];
};

__device__ __forceinline__ void preacc(const SmemP& sm, int w, int l, int nk,
                                       int ktl, float* acc) {
    const float* cqr = sm.cq + w * 16;
#pragma unroll
    for (int o = 0; o < 16; o++) acc[o] = cqr[o];
    if (ktl >= 0) {
        const float* ckr = sm.ck + l * 17;
        const float* tr = sm.tile + (sm.qi[w] * nk + sm.ki[l]) * 17;
#pragma unroll
        for (int o = 0; o < 16; o++) acc[o] += ckr[o] + tr[o];
        if (sm.mk[l] && sm.mq[w] && sm.uidk[l] == sm.uidq[w]) {
            float dx = sm.posk[l * 4 + 0] - sm.posq[w * 4 + 0];
            float dy = sm.posk[l * 4 + 1] - sm.posq[w * 4 + 1];
            float dz = sm.posk[l * 4 + 2] - sm.posq[w * 4 + 2];
            float dn = 1.f / (1.f + dx * dx + dy * dy + dz * dz);
#pragma unroll
            for (int o = 0; o < 16; o++)
                acc[o] += dx * sm.wposT[o] + dy * sm.wposT[16 + o] +
                          dz * sm.wposT[32 + o] + dn * sm.wdist[o] + sm.wmask[o];
        }
    }
}

__device__ __forceinline__ void zp_reduce_store(const SmemP& sm, float4 v, int lane,
                                                float* dst, int p) {
    float s = v.x + v.y + v.z + v.w;
    float q = v.x * v.x + v.y * v.y + v.z * v.z + v.w * v.w;
#pragma unroll
    for (int d = 16; d; d >>= 1) { s += __shfl_xor_sync(~0u, s, d); q += __shfl_xor_sync(~0u, q, d); }
    float mean = s * (1.f / 128.f);
    float rstd = rsqrtf(q * (1.f / 128.f) - mean * mean + 1e-5f);
    float4 g4 = ((const float4*)sm.lnzg)[lane];
    float4 b4 = ((const float4*)sm.lnzb)[lane];
    float n0 = (v.x - mean) * rstd * g4.x + b4.x;
    float n1 = (v.y - mean) * rstd * g4.y + b4.y;
    float n2 = (v.z - mean) * rstd * g4.z + b4.z;
    float n3 = (v.w - mean) * rstd * g4.w + b4.w;
    float vv[16];
#pragma unroll
    for (int o = 0; o < 16; o++) {
        float4 w = ((const float4*)(sm.wz2pT + o * 128))[lane];
        vv[o] = n0 * w.x + n1 * w.y + n2 * w.z + n3 * w.w;
    }
#pragma unroll
    for (int d = 0; d < 4; d++) {
        int half = 8 >> d;
        unsigned m = 1u << d;
        bool up = (lane & m) != 0;
        float tmp[8];
#pragma unroll
        for (int i = 0; i < 8; i++) {
            if (i < half) {
                float mine  = up ? vv[i + half] : vv[i];
                float sendv = up ? vv[i] : vv[i + half];
                tmp[i] = mine + __shfl_xor_sync(~0u, sendv, m);
            }
        }
#pragma unroll
        for (int i = 0; i < 8; i++) if (i < half) vv[i] = tmp[i];
    }
    vv[0] += __shfl_xor_sync(~0u, vv[0], 16);
    if (lane < 16) {
        int rev = ((lane & 1) << 3) | ((lane & 2) << 1) | ((lane & 4) >> 1) | ((lane & 8) >> 3);
        dst[p * 17 + rev] = vv[0];
    }
}

__global__ void __launch_bounds__(256, 2) p_kernel(
    const float* __restrict__ z, const float* __restrict__ pos,
    const int* __restrict__ maskw, const int* __restrict__ uid,
    const float* __restrict__ Wpos, const float* __restrict__ Wdist_,
    const float* __restrict__ Wmask_,
    const float* __restrict__ lnzg, const float* __restrict__ lnzb,
    const float* __restrict__ Wz2p,
    const float* __restrict__ Wm1, const float* __restrict__ Wm2,
    const float* __restrict__ Wm3,
    float* __restrict__ outp) {
    extern __shared__ char smraw[];
    SmemP& sm = *reinterpret_cast<SmemP*>(smraw);
    const int tid = threadIdx.x;
    const int k = blockIdx.x >> 1;
    const int half = blockIdx.x & 1;

    if (tid < 128) {
        int l = tid, a = k * 32 + l - 48;
        bool valid = (a >= 0 && a < NA);
        sm.kt[l]   = valid ? g_tok[a] : -1;
        sm.uidk[l] = valid ? uid[a]   : -1;
        sm.mk[l]   = valid ? (maskw[a] != 0) : 0;
        sm.posk[l * 4 + 0] = valid ? pos[a * 3 + 0] : 0.f;
        sm.posk[l * 4 + 1] = valid ? pos[a * 3 + 1] : 0.f;
        sm.posk[l * 4 + 2] = valid ? pos[a * 3 + 2] : 0.f;
    }
    if (tid < 32) {
        int a = k * 32 + tid;
        sm.qt[tid] = g_tok[a];
        sm.uidq[tid] = uid[a];
        sm.mq[tid] = (maskw[a] != 0);
        sm.posq[tid * 4 + 0] = pos[a * 3 + 0];
        sm.posq[tid * 4 + 1] = pos[a * 3 + 1];
        sm.posq[tid * 4 + 2] = pos[a * 3 + 2];
    }
    for (int i = tid; i < 128 * 16; i += 256) {
        int l = i >> 4, o = i & 15;
        int a = k * 32 + l - 48;
        sm.ck[l * 17 + o] = (a >= 0 && a < NA) ? g_ck[a * 16 + o] : 0.f;
    }
    for (int i = tid; i < 32 * 16; i += 256) sm.cq[i] = g_cq[(k * 32) * 16 + i];
    for (int i = tid; i < 16 * 128; i += 256) {
        int o = i >> 7, f = i & 127;
        sm.wz2pT[i] = Wz2p[f * 16 + o];
    }
    if (tid < 48) sm.wposT[tid] = Wpos[tid];
    if (tid >= 64 && tid < 80)  sm.wdist[tid - 64] = Wdist_[tid - 64];
    if (tid >= 96 && tid < 112) sm.wmask[tid - 96] = Wmask_[tid - 96];
    {
        int i = tid;
        float w1 = Wm1[i];
        float w2t = Wm2[(i & 15) * 16 + (i >> 4)];
        float w3 = Wm3[i];
        sm.wm1p[i]  = pk2(w1, w1);
        sm.wm2pT[i] = pk2(w2t, w2t);
        sm.wm3p[i]  = pk2(w3, w3);
    }
    for (int i = tid; i < 128; i += 256) { sm.lnzg[i] = lnzg[i]; sm.lnzb[i] = lnzb[i]; }
    __syncthreads();

    // parallel dedup: warp0 = q tokens; warps 1,2 = this CTA's two k-chunks
    if (tid < 32) {
        int t = sm.qt[tid];
        int prev = __shfl_up_sync(~0u, t, 1);
        bool bd = (tid == 0) || (t != prev);
        unsigned m = __ballot_sync(~0u, bd);
        int idx = __popc(m & (0xFFFFFFFFu >> (31 - tid))) - 1;
        sm.qi[tid] = idx;
        if (bd) sm.uqt[idx] = t;
        if (tid == 0) sm.nq = __popc(m);
    } else if (tid < 96) {
        int wrp = (tid - 32) >> 5;         // 0 or 1
        int c2 = half * 2 + wrp;
        int j = tid & 31;
        int l = c2 * 32 + j;
        int t = sm.kt[l];
        bool valid = (t >= 0);
        int prev = __shfl_up_sync(~0u, t, 1);
        bool bd = valid && (j == 0 || t != prev);
        unsigned m = __ballot_sync(~0u, bd);
        int idx = __popc(m & (0xFFFFFFFFu >> (31 - j))) - 1;
        sm.ki[l] = valid ? idx : -1;
        if (bd) sm.ukt[c2 * 32 + idx] = t;
        if (j == 0) sm.nkc[c2] = __popc(m);
    }
    __syncthreads();

    const int wid = tid >> 5, lane = tid & 31;
    const int nq = sm.nq;

    for (int lci = 0; lci < 2; lci++) {
        const int lc = half * 2 + lci;
        if (lci) __syncthreads();
        const int nk = sm.nkc[lc];
        const int npairs = nq * nk;

        for (int p = wid; p < npairs; p += 8) {
            int ti = sm.uqt[p / nk];
            int tj = sm.ukt[lc * 32 + p % nk];
            float4 v = ((const float4*)(z + ((size_t)ti * TT + tj) * 128))[lane];
            zp_reduce_store(sm, v, lane, sm.tile, p);
        }
        __syncthreads();

        const int l = lc * 32 + lane;
        const int ktl = sm.kt[l];
#pragma unroll 1
        for (int wi = 0; wi < 2; wi++) {
            const int w = wid + wi * 8;
            float accA[16], accB[16];
            preacc(sm, w, l, nk, ktl, accA);
            preacc(sm, w + 16, l, nk, ktl, accB);
            ull acc2[16];
#pragma unroll
            for (int o = 0; o < 16; o++) acc2[o] = pk2(accA[o], accB[o]);

            const ulonglong2* w1v = (const ulonglong2*)sm.wm1p;
            const ulonglong2* w2v = (const ulonglong2*)sm.wm2pT;
            const ulonglong2* w3v = (const ulonglong2*)sm.wm3p;

            ull t1[16];
#pragma unroll
            for (int j = 0; j < 16; j++) t1[j] = 0ull;
#pragma unroll
            for (int o = 0; o < 16; o++) {
                ull r2 = relu2(acc2[o]);
                const ulonglong2* row = w1v + o * 8;
#pragma unroll
                for (int jv = 0; jv < 8; jv++) {
                    ulonglong2 wv = row[jv];
                    t1[2 * jv]     = fma2(r2, wv.x, t1[2 * jv]);
                    t1[2 * jv + 1] = fma2(r2, wv.y, t1[2 * jv + 1]);
                }
            }
#pragma unroll
            for (int o = 0; o < 16; o++) t1[o] = relu2(t1[o]);

#pragma unroll
            for (int j = 0; j < 16; j++) {
                const ulonglong2* row2 = w2v + j * 8;
                ull s0 = 0ull, s1 = 0ull, s2 = 0ull, s3 = 0ull;
#pragma unroll
                for (int i = 0; i < 8; i += 2) {
                    ulonglong2 wa = row2[i], wb = row2[i + 1];
                    s0 = fma2(t1[2 * i],     wa.x, s0);
                    s1 = fma2(t1[2 * i + 1], wa.y, s1);
                    s2 = fma2(t1[2 * i + 2], wb.x, s2);
                    s3 = fma2(t1[2 * i + 3], wb.y, s3);
                }
                ull r2 = relu2(add2(add2(s0, s1), add2(s2, s3)));
                const ulonglong2* row3 = w3v + j * 8;
#pragma unroll
                for (int ov = 0; ov < 8; ov++) {
                    ulonglong2 wv = row3[ov];
                    acc2[2 * ov]     = fma2(r2, wv.x, acc2[2 * ov]);
                    acc2[2 * ov + 1] = fma2(r2, wv.y, acc2[2 * ov + 1]);
                }
            }
#pragma unroll
            for (int o = 0; o < 16; o++) upk2(acc2[o], accA[o], accB[o]);
            float* poA = outp + (((size_t)(k * 32 + w)) * 128 + l) * 16;
            float* poB = outp + (((size_t)(k * 32 + w + 16)) * 128 + l) * 16;
#pragma unroll
            for (int oq = 0; oq < 4; oq++) {
                float4 vA = { accA[oq * 4], accA[oq * 4 + 1], accA[oq * 4 + 2], accA[oq * 4 + 3] };
                float4 vB = { accB[oq * 4], accB[oq * 4 + 1], accB[oq * 4 + 2], accB[oq * 4 + 3] };
                reinterpret_cast<float4*>(poA)[oq] = vA;
                reinterpret_cast<float4*>(poB)[oq] = vB;
            }
        }
    }
}

extern "C" void kernel_launch(void* const* d_in, const int* in_sizes, int n_in,
                              void* d_out, int out_size) {
    const float* ref_pos      = (const float*)d_in[0];
    const float* ref_charge   = (const float*)d_in[1];
    const float* ref_element  = (const float*)d_in[2];
    const float* ref_chars    = (const float*)d_in[3];
    const int*   mask         = (const int*)d_in[4];
    const int*   uid          = (const int*)d_in[5];
    const float* a2t          = (const float*)d_in[6];
    const float* s_trunk      = (const float*)d_in[7];
    const float* z            = (const float*)d_in[8];
    const float* W_feat       = (const float*)d_in[9];
    const float* b_feat       = (const float*)d_in[10];
    const float* W_pos        = (const float*)d_in[11];
    const float* W_dist       = (const float*)d_in[12];
    const float* W_mask       = (const float*)d_in[13];
    const float* ln_s_g       = (const float*)d_in[14];
    const float* ln_s_b       = (const float*)d_in[15];
    const float* W_s2c        = (const float*)d_in[16];
    const float* ln_z_g       = (const float*)d_in[17];
    const float* ln_z_b       = (const float*)d_in[18];
    const float* W_z2p        = (const float*)d_in[19];
    const float* W_cq         = (const float*)d_in[20];
    const float* W_ck         = (const float*)d_in[21];
    const float* W_m1         = (const float*)d_in[22];
    const float* W_m2         = (const float*)d_in[23];
    const float* W_m3         = (const float*)d_in[24];

    float* out_q = (float*)d_out;
    float* out_c = out_q + (size_t)NA * AS;
    float* out_p = out_q + (size_t)2 * NA * AS;

    cudaFuncSetAttribute(p_kernel, cudaFuncAttributeMaxDynamicSharedMemorySize,
                         (int)sizeof(SmemP));

    s2c_kernel<<<64, 256>>>(s_trunk, ln_s_g, ln_s_b, W_s2c);
    c0_kernel<<<128, 256>>>(ref_pos, ref_charge, ref_element, ref_chars, a2t,
                            W_feat, b_feat, W_cq, W_ck, out_q, out_c);
    p_kernel<<<256, 256, sizeof(SmemP)>>>(z, ref_pos, mask, uid,
                                          W_pos, W_dist, W_mask,
                                          ln_z_g, ln_z_b, W_z2p,
                                          W_m1, W_m2, W_m3, out_p);
}